// round 5
// baseline (speedup 1.0000x reference)
#include <cuda_runtime.h>
#include <math.h>

// Problem dims
#define Bq   8
#define Nn   1000
#define CIN_ 16
#define Hh   64
#define Dd   16
#define XIN_ 80     // CIN + H
#define IG   240    // K * XIN (chebyshev-concat feature dim)
#define OG   128    // 2H (gate out)
#define OU   64     // H  (update out)

// Scratch (device globals: allocation-free rule)
__device__ float g_xg[3L * Bq * Nn * IG];   // [z][b][n][240]: [0:16]=x, [16:80]=state or z*state, [80:160]=t1, [160:240]=t2
__device__ float g_r [3L * Bq * Nn * Hh];   // reset gate

// ---------------------------------------------------------------------------
// Kernel 1: build xs = concat(x, state) into x_g slice [0:80)
// ---------------------------------------------------------------------------
__global__ void concat_kernel(const float* __restrict__ x1, const float* __restrict__ x2,
                              const float* __restrict__ x3,
                              const float* __restrict__ s1, const float* __restrict__ s2,
                              const float* __restrict__ s3) {
    const long total = 3L * Bq * Nn * XIN_;
    for (long idx = (long)blockIdx.x * blockDim.x + threadIdx.x; idx < total;
         idx += (long)gridDim.x * blockDim.x) {
        int c = (int)(idx % XIN_);
        long t = idx / XIN_;
        int n = (int)(t % Nn); t /= Nn;
        int b = (int)(t % Bq);
        int z = (int)(t / Bq);
        const float* x = (z == 0) ? x1 : (z == 1) ? x2 : x3;
        const float* s = (z == 0) ? s1 : (z == 1) ? s2 : s3;
        float v = (c < CIN_) ? x[((long)b * Nn + n) * CIN_ + c]
                             : s[((long)b * Nn + n) * Hh + (c - CIN_)];
        g_xg[(((long)z * Bq + b) * Nn + n) * IG + c] = v;
    }
}

// ---------------------------------------------------------------------------
// Kernel 2: graph propagation GEMM. For mode z, batch b:
//   out[n, c] = alpha * sum_m S_z[n,m] * xg[z,b,m, in_off+c]   (- xg[z,b,n,c] if sub)
// Tiled 64x80x16, 256 threads, 4x5 microtile.
// ---------------------------------------------------------------------------
#define BM 64
#define BK 16
#define BN 80
__global__ __launch_bounds__(256)
void spmm_kernel(const float* __restrict__ S1, const float* __restrict__ S2,
                 const float* __restrict__ S3, int in_off, int out_off,
                 float alpha, int sub) {
    int z = blockIdx.z, b = blockIdx.y;
    const float* S = (z == 0) ? S1 : (z == 1) ? S2 : S3;
    int n0 = blockIdx.x * BM;

    __shared__ float As[BM][BK + 1];
    __shared__ float Bs[BK][BN];

    float acc[4][5];
#pragma unroll
    for (int i = 0; i < 4; i++)
#pragma unroll
        for (int j = 0; j < 5; j++) acc[i][j] = 0.f;

    int tid = threadIdx.x;
    int tx = tid & 15, ty = tid >> 4;
    float* xbase = g_xg + ((long)z * Bq + b) * Nn * IG;
    const float* xin = xbase + in_off;

    for (int k0 = 0; k0 < Nn; k0 += BK) {
#pragma unroll
        for (int l = 0; l < 4; l++) {
            int idx = tid * 4 + l;
            int r = idx >> 4, c = idx & 15;
            int n = n0 + r, m = k0 + c;
            As[r][c] = (n < Nn && m < Nn) ? S[(long)n * Nn + m] : 0.f;
        }
#pragma unroll
        for (int l = 0; l < 5; l++) {
            int idx = tid * 5 + l;
            int r = idx / BN, c = idx % BN;
            int m = k0 + r;
            Bs[r][c] = (m < Nn) ? xin[(long)m * IG + c] : 0.f;
        }
        __syncthreads();
#pragma unroll
        for (int kk = 0; kk < BK; kk++) {
            float a[4], bb[5];
#pragma unroll
            for (int i = 0; i < 4; i++) a[i] = As[ty * 4 + i][kk];
#pragma unroll
            for (int j = 0; j < 5; j++) bb[j] = Bs[kk][tx * 5 + j];
#pragma unroll
            for (int i = 0; i < 4; i++)
#pragma unroll
                for (int j = 0; j < 5; j++)
                    acc[i][j] = fmaf(a[i], bb[j], acc[i][j]);
        }
        __syncthreads();
    }
#pragma unroll
    for (int i = 0; i < 4; i++) {
        int n = n0 + ty * 4 + i;
        if (n >= Nn) continue;
#pragma unroll
        for (int j = 0; j < 5; j++) {
            int c = tx * 5 + j;
            float v = alpha * acc[i][j];
            if (sub) v -= xbase[(long)n * IG + c];
            xbase[(long)n * IG + out_off + c] = v;
        }
    }
}

// ---------------------------------------------------------------------------
// Kernel 3: fused gate hypernet. Per block: G=10 nodes, all 8 batches.
//   zr[b,n,o] = sigmoid( sum_i xg[b,n,i] * (sum_d c[n,d] Wg[d,i,o]) + sum_d c[n,d] Bg[d,o] )
//   c[n,d] = emb[n,d]*me[d].  z-part -> xg[...,16+o] = z*state ; r-part -> g_r
// 128 threads: one output column o each. Dynamic smem: x tile [G][240][8] + c [G][16].
// ---------------------------------------------------------------------------
#define GG 10
#define GATE_SMEM ((GG * IG * 8 + GG * Dd) * 4)

__global__ __launch_bounds__(128)
void gate_kernel(const float* __restrict__ e1, const float* __restrict__ e2,
                 const float* __restrict__ e3, const float* __restrict__ me,
                 const float* __restrict__ Wg, const float* __restrict__ Bg,
                 const float* __restrict__ st1, const float* __restrict__ st2,
                 const float* __restrict__ st3) {
    extern __shared__ float sm[];
    float* x_s = sm;                     // [GG][IG][8]
    float* c_s = sm + GG * IG * 8;       // [GG][16]

    int z = blockIdx.y;
    int n0 = blockIdx.x * GG;
    const float* emb = (z == 0) ? e1 : (z == 1) ? e2 : e3;
    const float* st  = (z == 0) ? st1 : (z == 1) ? st2 : st3;

    int tid = threadIdx.x;
    // FIX (round 4): GG*Dd = 160 > blockDim (128). Previous `if (tid < 160)`
    // left c_s[128..159] (nodes g=8,9) uninitialized -> ~10% rel err.
    for (int idx = tid; idx < GG * Dd; idx += 128) {
        int g = idx >> 4, d = idx & 15;
        c_s[idx] = emb[(n0 + g) * Dd + d] * me[z * Dd + d];
    }
    for (int idx = tid; idx < GG * 8 * IG; idx += 128) {
        int i = idx % IG;
        int t = idx / IG;
        int g = t % GG, b = t / GG;
        x_s[(g * IG + i) * 8 + b] =
            g_xg[(((long)z * Bq + b) * Nn + n0 + g) * IG + i];
    }
    __syncthreads();

    int o = tid;  // 0..127
    float acc[GG][8];
#pragma unroll
    for (int g = 0; g < GG; g++)
#pragma unroll
        for (int b = 0; b < 8; b++) acc[g][b] = 0.f;

    for (int i = 0; i < IG; i++) {
        float wgv[16];
        const float* wp = Wg + (long)i * OG + o;
#pragma unroll
        for (int d = 0; d < 16; d++) wgv[d] = wp[(long)d * IG * OG];
#pragma unroll
        for (int g = 0; g < GG; g++) {
            const float4* cp = (const float4*)(c_s + g * 16);
            float4 c0 = cp[0], c1 = cp[1], c2 = cp[2], c3 = cp[3];
            float w = c0.x * wgv[0] + c0.y * wgv[1] + c0.z * wgv[2] + c0.w * wgv[3]
                    + c1.x * wgv[4] + c1.y * wgv[5] + c1.z * wgv[6] + c1.w * wgv[7]
                    + c2.x * wgv[8] + c2.y * wgv[9] + c2.z * wgv[10] + c2.w * wgv[11]
                    + c3.x * wgv[12] + c3.y * wgv[13] + c3.z * wgv[14] + c3.w * wgv[15];
            float4 xa = *(const float4*)(x_s + (g * IG + i) * 8);
            float4 xb = *(const float4*)(x_s + (g * IG + i) * 8 + 4);
            acc[g][0] = fmaf(w, xa.x, acc[g][0]);
            acc[g][1] = fmaf(w, xa.y, acc[g][1]);
            acc[g][2] = fmaf(w, xa.z, acc[g][2]);
            acc[g][3] = fmaf(w, xa.w, acc[g][3]);
            acc[g][4] = fmaf(w, xb.x, acc[g][4]);
            acc[g][5] = fmaf(w, xb.y, acc[g][5]);
            acc[g][6] = fmaf(w, xb.z, acc[g][6]);
            acc[g][7] = fmaf(w, xb.w, acc[g][7]);
        }
    }

#pragma unroll
    for (int g = 0; g < GG; g++) {
        int n = n0 + g;
        float bias = 0.f;
#pragma unroll
        for (int d = 0; d < 16; d++) bias += c_s[g * 16 + d] * Bg[d * OG + o];
#pragma unroll
        for (int b = 0; b < 8; b++) {
            float v = acc[g][b] + bias;
            float sg = 1.f / (1.f + expf(-v));
            if (o < Hh) {
                float stv = st[((long)b * Nn + n) * Hh + o];
                g_xg[(((long)z * Bq + b) * Nn + n) * IG + CIN_ + o] = sg * stv;
            } else {
                g_r[(((long)z * Bq + b) * Nn + n) * Hh + (o - Hh)] = sg;
            }
        }
    }
}

// ---------------------------------------------------------------------------
// Kernel 4: fused update hypernet + GRU mix.
//   hc = tanh(hypernet(Wu,Bu));  h = r*state + (1-r)*hc -> d_out
// 128 threads: o = tid&63, batch-half = tid>>6 (4 batches each).
// ---------------------------------------------------------------------------
__global__ __launch_bounds__(128)
void update_kernel(const float* __restrict__ e1, const float* __restrict__ e2,
                   const float* __restrict__ e3, const float* __restrict__ me,
                   const float* __restrict__ Wu, const float* __restrict__ Bu,
                   const float* __restrict__ st1, const float* __restrict__ st2,
                   const float* __restrict__ st3, float* __restrict__ out) {
    extern __shared__ float sm[];
    float* x_s = sm;
    float* c_s = sm + GG * IG * 8;

    int z = blockIdx.y;
    int n0 = blockIdx.x * GG;
    const float* emb = (z == 0) ? e1 : (z == 1) ? e2 : e3;
    const float* st  = (z == 0) ? st1 : (z == 1) ? st2 : st3;

    int tid = threadIdx.x;
    // FIX (round 4): same 160-vs-128 bug as gate_kernel.
    for (int idx = tid; idx < GG * Dd; idx += 128) {
        int g = idx >> 4, d = idx & 15;
        c_s[idx] = emb[(n0 + g) * Dd + d] * me[z * Dd + d];
    }
    for (int idx = tid; idx < GG * 8 * IG; idx += 128) {
        int i = idx % IG;
        int t = idx / IG;
        int g = t % GG, b = t / GG;
        x_s[(g * IG + i) * 8 + b] =
            g_xg[(((long)z * Bq + b) * Nn + n0 + g) * IG + i];
    }
    __syncthreads();

    int o  = tid & 63;
    int bh = tid >> 6;  // 0 or 1
    float acc[GG][4];
#pragma unroll
    for (int g = 0; g < GG; g++)
#pragma unroll
        for (int j = 0; j < 4; j++) acc[g][j] = 0.f;

    for (int i = 0; i < IG; i++) {
        float wgv[16];
        const float* wp = Wu + (long)i * OU + o;
#pragma unroll
        for (int d = 0; d < 16; d++) wgv[d] = wp[(long)d * IG * OU];
#pragma unroll
        for (int g = 0; g < GG; g++) {
            const float4* cp = (const float4*)(c_s + g * 16);
            float4 c0 = cp[0], c1 = cp[1], c2 = cp[2], c3 = cp[3];
            float w = c0.x * wgv[0] + c0.y * wgv[1] + c0.z * wgv[2] + c0.w * wgv[3]
                    + c1.x * wgv[4] + c1.y * wgv[5] + c1.z * wgv[6] + c1.w * wgv[7]
                    + c2.x * wgv[8] + c2.y * wgv[9] + c2.z * wgv[10] + c2.w * wgv[11]
                    + c3.x * wgv[12] + c3.y * wgv[13] + c3.z * wgv[14] + c3.w * wgv[15];
            float4 xa = *(const float4*)(x_s + (g * IG + i) * 8 + bh * 4);
            acc[g][0] = fmaf(w, xa.x, acc[g][0]);
            acc[g][1] = fmaf(w, xa.y, acc[g][1]);
            acc[g][2] = fmaf(w, xa.z, acc[g][2]);
            acc[g][3] = fmaf(w, xa.w, acc[g][3]);
        }
    }

#pragma unroll
    for (int g = 0; g < GG; g++) {
        int n = n0 + g;
        float bias = 0.f;
#pragma unroll
        for (int d = 0; d < 16; d++) bias += c_s[g * 16 + d] * Bu[d * OU + o];
#pragma unroll
        for (int j = 0; j < 4; j++) {
            int b = bh * 4 + j;
            float hc = tanhf(acc[g][j] + bias);
            long hidx = (((long)z * Bq + b) * Nn + n) * Hh + o;
            float r = g_r[hidx];
            float stv = st[((long)b * Nn + n) * Hh + o];
            out[hidx] = r * stv + (1.f - r) * hc;
        }
    }
}

// ---------------------------------------------------------------------------
extern "C" void kernel_launch(void* const* d_in, const int* in_sizes, int n_in,
                              void* d_out, int out_size) {
    const float* x1 = (const float*)d_in[0];
    const float* x2 = (const float*)d_in[1];
    const float* x3 = (const float*)d_in[2];
    const float* s1 = (const float*)d_in[3];
    const float* s2 = (const float*)d_in[4];
    const float* s3 = (const float*)d_in[5];
    const float* A1 = (const float*)d_in[6];
    const float* A2 = (const float*)d_in[7];
    const float* A3 = (const float*)d_in[8];
    const float* e1 = (const float*)d_in[9];
    const float* e2 = (const float*)d_in[10];
    const float* e3 = (const float*)d_in[11];
    const float* me = (const float*)d_in[12];
    const float* Wg = (const float*)d_in[13];
    const float* Bg = (const float*)d_in[14];
    const float* Wu = (const float*)d_in[15];
    const float* Bu = (const float*)d_in[16];
    float* out = (float*)d_out;

    cudaFuncSetAttribute((const void*)gate_kernel,
                         cudaFuncAttributeMaxDynamicSharedMemorySize, GATE_SMEM);
    cudaFuncSetAttribute((const void*)update_kernel,
                         cudaFuncAttributeMaxDynamicSharedMemorySize, GATE_SMEM);

    dim3 gs((Nn + BM - 1) / BM, Bq, 3);   // 16 x 8 x 3
    dim3 hg(Nn / GG, 3);                  // 100 x 3

    // ---- gate GCN ----
    concat_kernel<<<512, 256>>>(x1, x2, x3, s1, s2, s3);
    spmm_kernel<<<gs, 256>>>(A1, A2, A3, 0, 80, 1.f, 0);    // t1 = S @ xs
    spmm_kernel<<<gs, 256>>>(A1, A2, A3, 80, 160, 2.f, 1);  // t2 = 2 S t1 - xs
    gate_kernel<<<hg, 128, GATE_SMEM>>>(e1, e2, e3, me, Wg, Bg, s1, s2, s3);
    // ---- candidate GCN (xs2 = [x, z*state] already in slice [0:80)) ----
    spmm_kernel<<<gs, 256>>>(A1, A2, A3, 0, 80, 1.f, 0);
    spmm_kernel<<<gs, 256>>>(A1, A2, A3, 80, 160, 2.f, 1);
    update_kernel<<<hg, 128, GATE_SMEM>>>(e1, e2, e3, me, Wu, Bu, s1, s2, s3, out);
}

// round 6
// speedup vs baseline: 1.0449x; 1.0449x over previous
#include <cuda_runtime.h>
#include <math.h>

// Problem dims
#define Bq   8
#define Nn   1000
#define CIN_ 16
#define Hh   64
#define Dd   16
#define XIN_ 80     // CIN + H
#define IG   240    // K * XIN
#define OG   128    // 2H
#define OU   64     // H

// Scratch (device globals: allocation-free rule)
__device__ float g_xg[3L * Bq * Nn * IG];   // [z][b][n][240]
__device__ float g_r [3L * Bq * Nn * Hh];   // reset gate

// ---------------------------------------------------------------------------
// Kernel 1: xs = concat(x, state) -> x_g[0:80)
// ---------------------------------------------------------------------------
__global__ void concat_kernel(const float* __restrict__ x1, const float* __restrict__ x2,
                              const float* __restrict__ x3,
                              const float* __restrict__ s1, const float* __restrict__ s2,
                              const float* __restrict__ s3) {
    const long total = 3L * Bq * Nn * XIN_;
    for (long idx = (long)blockIdx.x * blockDim.x + threadIdx.x; idx < total;
         idx += (long)gridDim.x * blockDim.x) {
        int c = (int)(idx % XIN_);
        long t = idx / XIN_;
        int n = (int)(t % Nn); t /= Nn;
        int b = (int)(t % Bq);
        int z = (int)(t / Bq);
        const float* x = (z == 0) ? x1 : (z == 1) ? x2 : x3;
        const float* s = (z == 0) ? s1 : (z == 1) ? s2 : s3;
        float v = (c < CIN_) ? x[((long)b * Nn + n) * CIN_ + c]
                             : s[((long)b * Nn + n) * Hh + (c - CIN_)];
        g_xg[(((long)z * Bq + b) * Nn + n) * IG + c] = v;
    }
}

// ---------------------------------------------------------------------------
// Kernel 2: graph propagation GEMM (at fp32 SIMT FMA roofline; unchanged)
// ---------------------------------------------------------------------------
#define BM 64
#define BK 16
#define BN 80
__global__ __launch_bounds__(256)
void spmm_kernel(const float* __restrict__ S1, const float* __restrict__ S2,
                 const float* __restrict__ S3, int in_off, int out_off,
                 float alpha, int sub) {
    int z = blockIdx.z, b = blockIdx.y;
    const float* S = (z == 0) ? S1 : (z == 1) ? S2 : S3;
    int n0 = blockIdx.x * BM;

    __shared__ float As[BM][BK + 1];
    __shared__ float Bs[BK][BN];

    float acc[4][5];
#pragma unroll
    for (int i = 0; i < 4; i++)
#pragma unroll
        for (int j = 0; j < 5; j++) acc[i][j] = 0.f;

    int tid = threadIdx.x;
    int tx = tid & 15, ty = tid >> 4;
    float* xbase = g_xg + ((long)z * Bq + b) * Nn * IG;
    const float* xin = xbase + in_off;

    for (int k0 = 0; k0 < Nn; k0 += BK) {
#pragma unroll
        for (int l = 0; l < 4; l++) {
            int idx = tid * 4 + l;
            int r = idx >> 4, c = idx & 15;
            int n = n0 + r, m = k0 + c;
            As[r][c] = (n < Nn && m < Nn) ? S[(long)n * Nn + m] : 0.f;
        }
#pragma unroll
        for (int l = 0; l < 5; l++) {
            int idx = tid * 5 + l;
            int r = idx / BN, c = idx % BN;
            int m = k0 + r;
            Bs[r][c] = (m < Nn) ? xin[(long)m * IG + c] : 0.f;
        }
        __syncthreads();
#pragma unroll
        for (int kk = 0; kk < BK; kk++) {
            float a[4], bb[5];
#pragma unroll
            for (int i = 0; i < 4; i++) a[i] = As[ty * 4 + i][kk];
#pragma unroll
            for (int j = 0; j < 5; j++) bb[j] = Bs[kk][tx * 5 + j];
#pragma unroll
            for (int i = 0; i < 4; i++)
#pragma unroll
                for (int j = 0; j < 5; j++)
                    acc[i][j] = fmaf(a[i], bb[j], acc[i][j]);
        }
        __syncthreads();
    }
#pragma unroll
    for (int i = 0; i < 4; i++) {
        int n = n0 + ty * 4 + i;
        if (n >= Nn) continue;
#pragma unroll
        for (int j = 0; j < 5; j++) {
            int c = tx * 5 + j;
            float v = alpha * acc[i][j];
            if (sub) v -= xbase[(long)n * IG + c];
            xbase[(long)n * IG + out_off + c] = v;
        }
    }
}

// ---------------------------------------------------------------------------
// Kernel 3: fused gate hypernet. R5: GG=4 (regs: acc 32 + c 64), wgv prefetch,
// 31KB smem -> 3 blocks/SM (launch_bounds(128,3)).
// ---------------------------------------------------------------------------
#define GGG 4
#define GATE_SMEM ((GGG * IG * 8 + GGG * Dd) * 4)

__global__ __launch_bounds__(128, 3)
void gate_kernel(const float* __restrict__ e1, const float* __restrict__ e2,
                 const float* __restrict__ e3, const float* __restrict__ me,
                 const float* __restrict__ Wg, const float* __restrict__ Bg,
                 const float* __restrict__ st1, const float* __restrict__ st2,
                 const float* __restrict__ st3) {
    extern __shared__ float sm[];
    float* x_s = sm;                       // [GGG][IG][8]
    float* c_s = sm + GGG * IG * 8;        // [GGG][16]

    int z = blockIdx.y;
    int n0 = blockIdx.x * GGG;
    const float* emb = (z == 0) ? e1 : (z == 1) ? e2 : e3;
    const float* st  = (z == 0) ? st1 : (z == 1) ? st2 : st3;

    int tid = threadIdx.x;
    if (tid < GGG * Dd) {  // 64 <= 128: single shot
        int g = tid >> 4, d = tid & 15;
        c_s[tid] = emb[(n0 + g) * Dd + d] * me[z * Dd + d];
    }
    for (int idx = tid; idx < GGG * 8 * IG; idx += 128) {
        int i = idx % IG;
        int t = idx / IG;
        int g = t % GGG, b = t / GGG;
        x_s[(g * IG + i) * 8 + b] =
            g_xg[(((long)z * Bq + b) * Nn + n0 + g) * IG + i];
    }
    __syncthreads();

    int o = tid;  // 0..127
    // hoist per-node coefficients into registers
    float4 cr[GGG][4];
#pragma unroll
    for (int g = 0; g < GGG; g++) {
        const float4* cp = (const float4*)(c_s + g * 16);
#pragma unroll
        for (int q = 0; q < 4; q++) cr[g][q] = cp[q];
    }

    float acc[GGG][8];
#pragma unroll
    for (int g = 0; g < GGG; g++)
#pragma unroll
        for (int b = 0; b < 8; b++) acc[g][b] = 0.f;

    // double-buffered pool row: wgv = current, wnx = next i
    float wgv[16], wnx[16];
    {
        const float* wp = Wg + o;  // i = 0
#pragma unroll
        for (int d = 0; d < 16; d++) wnx[d] = wp[(long)d * IG * OG];
    }

    for (int i = 0; i < IG; i++) {
#pragma unroll
        for (int d = 0; d < 16; d++) wgv[d] = wnx[d];
        int ip = (i + 1 < IG) ? (i + 1) : i;
        const float* wp = Wg + (long)ip * OG + o;
#pragma unroll
        for (int d = 0; d < 16; d++) wnx[d] = wp[(long)d * IG * OG];

#pragma unroll
        for (int g = 0; g < GGG; g++) {
            float4 c0 = cr[g][0], c1 = cr[g][1], c2 = cr[g][2], c3 = cr[g][3];
            float w = c0.x * wgv[0] + c0.y * wgv[1] + c0.z * wgv[2] + c0.w * wgv[3]
                    + c1.x * wgv[4] + c1.y * wgv[5] + c1.z * wgv[6] + c1.w * wgv[7]
                    + c2.x * wgv[8] + c2.y * wgv[9] + c2.z * wgv[10] + c2.w * wgv[11]
                    + c3.x * wgv[12] + c3.y * wgv[13] + c3.z * wgv[14] + c3.w * wgv[15];
            float4 xa = *(const float4*)(x_s + (g * IG + i) * 8);
            float4 xb = *(const float4*)(x_s + (g * IG + i) * 8 + 4);
            acc[g][0] = fmaf(w, xa.x, acc[g][0]);
            acc[g][1] = fmaf(w, xa.y, acc[g][1]);
            acc[g][2] = fmaf(w, xa.z, acc[g][2]);
            acc[g][3] = fmaf(w, xa.w, acc[g][3]);
            acc[g][4] = fmaf(w, xb.x, acc[g][4]);
            acc[g][5] = fmaf(w, xb.y, acc[g][5]);
            acc[g][6] = fmaf(w, xb.z, acc[g][6]);
            acc[g][7] = fmaf(w, xb.w, acc[g][7]);
        }
    }

#pragma unroll
    for (int g = 0; g < GGG; g++) {
        int n = n0 + g;
        float4 c0 = cr[g][0], c1 = cr[g][1], c2 = cr[g][2], c3 = cr[g][3];
        const float* bp = Bg + o;
        float bias = c0.x * bp[0] + c0.y * bp[OG] + c0.z * bp[2 * OG] + c0.w * bp[3 * OG]
                   + c1.x * bp[4 * OG] + c1.y * bp[5 * OG] + c1.z * bp[6 * OG] + c1.w * bp[7 * OG]
                   + c2.x * bp[8 * OG] + c2.y * bp[9 * OG] + c2.z * bp[10 * OG] + c2.w * bp[11 * OG]
                   + c3.x * bp[12 * OG] + c3.y * bp[13 * OG] + c3.z * bp[14 * OG] + c3.w * bp[15 * OG];
#pragma unroll
        for (int b = 0; b < 8; b++) {
            float v = acc[g][b] + bias;
            float sg = 1.f / (1.f + __expf(-v));
            if (o < Hh) {
                float stv = st[((long)b * Nn + n) * Hh + o];
                g_xg[(((long)z * Bq + b) * Nn + n) * IG + CIN_ + o] = sg * stv;
            } else {
                g_r[(((long)z * Bq + b) * Nn + n) * Hh + (o - Hh)] = sg;
            }
        }
    }
}

// ---------------------------------------------------------------------------
// Kernel 4: fused update hypernet + GRU mix. R5: threads = (g-half, o in [0,64)).
// Combine computed ONCE per (g,i,o) (was duplicated per batch-half).
// GG=8 nodes/block, 4 per half. 62KB smem -> 3 blocks/SM.
// ---------------------------------------------------------------------------
#define GGU 8
#define UPD_SMEM ((GGU * IG * 8 + GGU * Dd) * 4)

__global__ __launch_bounds__(128, 3)
void update_kernel(const float* __restrict__ e1, const float* __restrict__ e2,
                   const float* __restrict__ e3, const float* __restrict__ me,
                   const float* __restrict__ Wu, const float* __restrict__ Bu,
                   const float* __restrict__ st1, const float* __restrict__ st2,
                   const float* __restrict__ st3, float* __restrict__ out) {
    extern __shared__ float sm[];
    float* x_s = sm;                       // [GGU][IG][8]
    float* c_s = sm + GGU * IG * 8;        // [GGU][16]

    int z = blockIdx.y;
    int n0 = blockIdx.x * GGU;
    const float* emb = (z == 0) ? e1 : (z == 1) ? e2 : e3;
    const float* st  = (z == 0) ? st1 : (z == 1) ? st2 : st3;

    int tid = threadIdx.x;
    if (tid < GGU * Dd) {  // 128 threads cover 128 entries
        int g = tid >> 4, d = tid & 15;
        c_s[tid] = emb[(n0 + g) * Dd + d] * me[z * Dd + d];
    }
    for (int idx = tid; idx < GGU * 8 * IG; idx += 128) {
        int i = idx % IG;
        int t = idx / IG;
        int g = t % GGU, b = t / GGU;
        x_s[(g * IG + i) * 8 + b] =
            g_xg[(((long)z * Bq + b) * Nn + n0 + g) * IG + i];
    }
    __syncthreads();

    int o  = tid & 63;        // output column
    int gh = tid >> 6;        // node half: g = gh*4 + g'
    int gbase = gh * 4;

    float4 cr[4][4];
#pragma unroll
    for (int g = 0; g < 4; g++) {
        const float4* cp = (const float4*)(c_s + (gbase + g) * 16);
#pragma unroll
        for (int q = 0; q < 4; q++) cr[g][q] = cp[q];
    }

    float acc[4][8];
#pragma unroll
    for (int g = 0; g < 4; g++)
#pragma unroll
        for (int b = 0; b < 8; b++) acc[g][b] = 0.f;

    float wgv[16], wnx[16];
    {
        const float* wp = Wu + o;
#pragma unroll
        for (int d = 0; d < 16; d++) wnx[d] = wp[(long)d * IG * OU];
    }

    for (int i = 0; i < IG; i++) {
#pragma unroll
        for (int d = 0; d < 16; d++) wgv[d] = wnx[d];
        int ip = (i + 1 < IG) ? (i + 1) : i;
        const float* wp = Wu + (long)ip * OU + o;
#pragma unroll
        for (int d = 0; d < 16; d++) wnx[d] = wp[(long)d * IG * OU];

#pragma unroll
        for (int g = 0; g < 4; g++) {
            float4 c0 = cr[g][0], c1 = cr[g][1], c2 = cr[g][2], c3 = cr[g][3];
            float w = c0.x * wgv[0] + c0.y * wgv[1] + c0.z * wgv[2] + c0.w * wgv[3]
                    + c1.x * wgv[4] + c1.y * wgv[5] + c1.z * wgv[6] + c1.w * wgv[7]
                    + c2.x * wgv[8] + c2.y * wgv[9] + c2.z * wgv[10] + c2.w * wgv[11]
                    + c3.x * wgv[12] + c3.y * wgv[13] + c3.z * wgv[14] + c3.w * wgv[15];
            const float* xp = x_s + ((gbase + g) * IG + i) * 8;
            float4 xa = *(const float4*)(xp);
            float4 xb = *(const float4*)(xp + 4);
            acc[g][0] = fmaf(w, xa.x, acc[g][0]);
            acc[g][1] = fmaf(w, xa.y, acc[g][1]);
            acc[g][2] = fmaf(w, xa.z, acc[g][2]);
            acc[g][3] = fmaf(w, xa.w, acc[g][3]);
            acc[g][4] = fmaf(w, xb.x, acc[g][4]);
            acc[g][5] = fmaf(w, xb.y, acc[g][5]);
            acc[g][6] = fmaf(w, xb.z, acc[g][6]);
            acc[g][7] = fmaf(w, xb.w, acc[g][7]);
        }
    }

#pragma unroll
    for (int g = 0; g < 4; g++) {
        int n = n0 + gbase + g;
        float4 c0 = cr[g][0], c1 = cr[g][1], c2 = cr[g][2], c3 = cr[g][3];
        const float* bp = Bu + o;
        float bias = c0.x * bp[0] + c0.y * bp[OU] + c0.z * bp[2 * OU] + c0.w * bp[3 * OU]
                   + c1.x * bp[4 * OU] + c1.y * bp[5 * OU] + c1.z * bp[6 * OU] + c1.w * bp[7 * OU]
                   + c2.x * bp[8 * OU] + c2.y * bp[9 * OU] + c2.z * bp[10 * OU] + c2.w * bp[11 * OU]
                   + c3.x * bp[12 * OU] + c3.y * bp[13 * OU] + c3.z * bp[14 * OU] + c3.w * bp[15 * OU];
#pragma unroll
        for (int b = 0; b < 8; b++) {
            float hc = tanhf(acc[g][b] + bias);
            long hidx = (((long)z * Bq + b) * Nn + n) * Hh + o;
            float r = g_r[hidx];
            float stv = st[((long)b * Nn + n) * Hh + o];
            out[hidx] = r * stv + (1.f - r) * hc;
        }
    }
}

// ---------------------------------------------------------------------------
extern "C" void kernel_launch(void* const* d_in, const int* in_sizes, int n_in,
                              void* d_out, int out_size) {
    const float* x1 = (const float*)d_in[0];
    const float* x2 = (const float*)d_in[1];
    const float* x3 = (const float*)d_in[2];
    const float* s1 = (const float*)d_in[3];
    const float* s2 = (const float*)d_in[4];
    const float* s3 = (const float*)d_in[5];
    const float* A1 = (const float*)d_in[6];
    const float* A2 = (const float*)d_in[7];
    const float* A3 = (const float*)d_in[8];
    const float* e1 = (const float*)d_in[9];
    const float* e2 = (const float*)d_in[10];
    const float* e3 = (const float*)d_in[11];
    const float* me = (const float*)d_in[12];
    const float* Wg = (const float*)d_in[13];
    const float* Bg = (const float*)d_in[14];
    const float* Wu = (const float*)d_in[15];
    const float* Bu = (const float*)d_in[16];
    float* out = (float*)d_out;

    cudaFuncSetAttribute((const void*)gate_kernel,
                         cudaFuncAttributeMaxDynamicSharedMemorySize, GATE_SMEM);
    cudaFuncSetAttribute((const void*)update_kernel,
                         cudaFuncAttributeMaxDynamicSharedMemorySize, UPD_SMEM);

    dim3 gs((Nn + BM - 1) / BM, Bq, 3);   // 16 x 8 x 3
    dim3 gg(Nn / GGG, 3);                 // 250 x 3
    dim3 gu(Nn / GGU, 3);                 // 125 x 3

    // ---- gate GCN ----
    concat_kernel<<<512, 256>>>(x1, x2, x3, s1, s2, s3);
    spmm_kernel<<<gs, 256>>>(A1, A2, A3, 0, 80, 1.f, 0);    // t1 = S @ xs
    spmm_kernel<<<gs, 256>>>(A1, A2, A3, 80, 160, 2.f, 1);  // t2 = 2 S t1 - xs
    gate_kernel<<<gg, 128, GATE_SMEM>>>(e1, e2, e3, me, Wg, Bg, s1, s2, s3);
    // ---- candidate GCN (xs2 = [x, z*state] already in slice [0:80)) ----
    spmm_kernel<<<gs, 256>>>(A1, A2, A3, 0, 80, 1.f, 0);
    spmm_kernel<<<gs, 256>>>(A1, A2, A3, 80, 160, 2.f, 1);
    update_kernel<<<gu, 128, UPD_SMEM>>>(e1, e2, e3, me, Wu, Bu, s1, s2, s3, out);
}

// round 10
// speedup vs baseline: 1.6849x; 1.6125x over previous
#include <cuda_runtime.h>
#include <math.h>
#include <stdint.h>

// Problem dims
#define Bq   8
#define Nn   1000
#define CIN_ 16
#define Hh   64
#define Dd   16
#define XIN_ 80     // CIN + H
#define IG   240    // K * XIN
#define OG   128    // 2H
#define OU   64     // H
#define NCOL 640    // Bq * XIN : batched GEMM N dimension

// Scratch (device globals: allocation-free rule)
__device__ float g_xg[3L * Bq * Nn * IG];    // [z][b][n][240]
__device__ float g_r [3L * Bq * Nn * Hh];    // reset gate
__device__ float g_P0[3L * NCOL * Nn];       // packed operand [z][col][k] (col = b*80+c)
__device__ float g_P1[3L * NCOL * Nn];       // packed t1

__device__ __forceinline__ float f2tf32(float v) {
    float o;
    asm("cvt.rna.tf32.f32 %0, %1;" : "=f"(o) : "f"(v));
    return o;
}

__device__ __forceinline__ void mma_tf32(float* c, const uint32_t* a,
                                         uint32_t b0, uint32_t b1) {
    asm volatile(
        "mma.sync.aligned.m16n8k8.row.col.f32.tf32.tf32.f32 "
        "{%0,%1,%2,%3}, {%4,%5,%6,%7}, {%8,%9}, {%0,%1,%2,%3};"
        : "+f"(c[0]), "+f"(c[1]), "+f"(c[2]), "+f"(c[3])
        : "r"(a[0]), "r"(a[1]), "r"(a[2]), "r"(a[3]), "r"(b0), "r"(b1));
}

// ===========================================================================
// Kernel 1: xs = concat(x, state) -> g_xg[0:80) AND packed g_P0[z][col][k]
// ===========================================================================
__global__ void concat_kernel(const float* __restrict__ x1, const float* __restrict__ x2,
                              const float* __restrict__ x3,
                              const float* __restrict__ s1, const float* __restrict__ s2,
                              const float* __restrict__ s3) {
    const long total = 3L * Bq * Nn * XIN_;
    for (long idx = (long)blockIdx.x * blockDim.x + threadIdx.x; idx < total;
         idx += (long)gridDim.x * blockDim.x) {
        int c = (int)(idx % XIN_);
        long t = idx / XIN_;
        int n = (int)(t % Nn); t /= Nn;
        int b = (int)(t % Bq);
        int z = (int)(t / Bq);
        const float* x = (z == 0) ? x1 : (z == 1) ? x2 : x3;
        const float* s = (z == 0) ? s1 : (z == 1) ? s2 : s3;
        float v = (c < CIN_) ? x[((long)b * Nn + n) * CIN_ + c]
                             : s[((long)b * Nn + n) * Hh + (c - CIN_)];
        g_xg[(((long)z * Bq + b) * Nn + n) * IG + c] = v;
        g_P0[((long)z * NCOL + b * XIN_ + c) * Nn + n] = v;
    }
}

// ===========================================================================
// Kernel 2: tf32 mma.sync GEMM stage (portable PTX; tcgen05 is rejected by the
// harness's compute_103 virtual target).
//   D[m, col] = S_z[m, :] @ Pin[z][col][:]   (M=1000, N=640, K=1000)
//   epilogue: v = alpha*D - (sub ? Pprev : 0) -> g_xg[..., out_off + c]; opt Pout.
// CTA tile 128x128, Kc=32, 256 threads (8 warps, 4x2), warp tile 32x64.
// Single smem buffer + register prefetch of next chunk.
// ===========================================================================
#define KC    32
#define LDK   36   // padded k-stride (floats)

__global__ __launch_bounds__(256)
void gemm_tf32_kernel(const float* __restrict__ S1, const float* __restrict__ S2,
                      const float* __restrict__ S3,
                      const float* __restrict__ Pin, const float* __restrict__ Pprev,
                      float* __restrict__ Pout, int out_off, float alpha, int sub) {
    __shared__ __align__(16) float As[128 * LDK];
    __shared__ __align__(16) float Bs[128 * LDK];

    int z = blockIdx.z;
    const float* S = (z == 0) ? S1 : (z == 1) ? S2 : S3;
    int m0 = blockIdx.x * 128;
    int nt = blockIdx.y;
    const float* Pz = Pin + (long)z * NCOL * Nn;

    int tid = threadIdx.x;
    int wid = tid >> 5, lane = tid & 31;
    int warp_m = wid & 3, warp_n = wid >> 2;      // 4 x 2 warp grid
    int g = lane >> 2, tig = lane & 3;            // mma group / thread-in-group

    float acc[2][8][4];
#pragma unroll
    for (int fm = 0; fm < 2; fm++)
#pragma unroll
        for (int fn = 0; fn < 8; fn++)
#pragma unroll
            for (int q = 0; q < 4; q++) acc[fm][fn][q] = 0.f;

    // gmem staging: thread covers 4 float4 of A and 4 of B per chunk
    // linear = tid + l*256 ; row = linear>>3 (0..127), c4 = linear&7 -> k0 = c4*4
    float4 ra[4], rb[4];
    const int NCHUNK = 32;   // ceil(1000/32)

    auto load_chunk = [&](int j) {
        int kbase = j * KC;
#pragma unroll
        for (int l = 0; l < 4; l++) {
            int linear = tid + l * 256;
            int row = linear >> 3, c4 = linear & 7;
            int k0 = kbase + c4 * 4;
            bool kok = (k0 < Nn);     // Nn % 4 == 0: float4 fully valid or fully not
            float4 va = make_float4(0.f, 0.f, 0.f, 0.f);
            int m = m0 + row;
            if (kok && m < Nn) va = *(const float4*)(S + (long)m * Nn + k0);
            va.x = f2tf32(va.x); va.y = f2tf32(va.y);
            va.z = f2tf32(va.z); va.w = f2tf32(va.w);
            ra[l] = va;
            float4 vb = make_float4(0.f, 0.f, 0.f, 0.f);
            int gc = nt * 128 + row;  // always < 640
            if (kok) vb = *(const float4*)(Pz + (long)gc * Nn + k0);
            vb.x = f2tf32(vb.x); vb.y = f2tf32(vb.y);
            vb.z = f2tf32(vb.z); vb.w = f2tf32(vb.w);
            rb[l] = vb;
        }
    };

    load_chunk(0);

    for (int j = 0; j < NCHUNK; j++) {
        __syncthreads();   // previous chunk's compute done
#pragma unroll
        for (int l = 0; l < 4; l++) {
            int linear = tid + l * 256;
            int row = linear >> 3, c4 = linear & 7;
            *(float4*)(As + row * LDK + c4 * 4) = ra[l];
            *(float4*)(Bs + row * LDK + c4 * 4) = rb[l];
        }
        __syncthreads();
        if (j + 1 < NCHUNK) load_chunk(j + 1);  // prefetch overlaps MMA below

#pragma unroll
        for (int ks = 0; ks < 4; ks++) {
            int kk = ks * 8;
            uint32_t afr[2][4];
#pragma unroll
            for (int fm = 0; fm < 2; fm++) {
                int rm = warp_m * 32 + fm * 16;
                const float* ab = As + (rm + g) * LDK + kk + tig;
                afr[fm][0] = __float_as_uint(ab[0]);
                afr[fm][1] = __float_as_uint(ab[8 * LDK]);
                afr[fm][2] = __float_as_uint(ab[4]);
                afr[fm][3] = __float_as_uint(ab[8 * LDK + 4]);
            }
#pragma unroll
            for (int fn = 0; fn < 8; fn++) {
                int nb = warp_n * 64 + fn * 8 + g;
                const float* bb = Bs + nb * LDK + kk + tig;
                uint32_t b0 = __float_as_uint(bb[0]);
                uint32_t b1 = __float_as_uint(bb[4]);
                mma_tf32(acc[0][fn], afr[0], b0, b1);
                mma_tf32(acc[1][fn], afr[1], b0, b1);
            }
        }
    }

    // ---- epilogue: v = alpha*acc - (sub ? Pprev : 0) -> g_xg (+ Pout) ----
    const float* Pprev_z = sub ? (Pprev + (long)z * NCOL * Nn) : nullptr;
    float* Pout_z = Pout ? (Pout + (long)z * NCOL * Nn) : nullptr;
#pragma unroll
    for (int fm = 0; fm < 2; fm++) {
#pragma unroll
        for (int fn = 0; fn < 8; fn++) {
            int m  = m0 + warp_m * 32 + fm * 16 + g;
            int gc = nt * 128 + warp_n * 64 + fn * 8 + tig * 2;
#pragma unroll
            for (int q = 0; q < 4; q++) {
                int mm = m + ((q >= 2) ? 8 : 0);
                int cc = gc + (q & 1);
                if (mm >= Nn) continue;
                float v = alpha * acc[fm][fn][q];
                if (sub) v -= Pprev_z[(long)cc * Nn + mm];
                int b = cc / XIN_, c = cc % XIN_;
                g_xg[(((long)z * Bq + b) * Nn + mm) * IG + out_off + c] = v;
                if (Pout_z) Pout_z[(long)cc * Nn + mm] = v;
            }
        }
    }
}

// ===========================================================================
// Kernel 3: fused gate hypernet (also writes packed z*state into P0)
// ===========================================================================
#define GGG 4
#define GATE_SMEM ((GGG * IG * 8 + GGG * Dd) * 4)

__global__ __launch_bounds__(128, 3)
void gate_kernel(const float* __restrict__ e1, const float* __restrict__ e2,
                 const float* __restrict__ e3, const float* __restrict__ me,
                 const float* __restrict__ Wg, const float* __restrict__ Bg,
                 const float* __restrict__ st1, const float* __restrict__ st2,
                 const float* __restrict__ st3) {
    extern __shared__ float sm[];
    float* x_s = sm;                       // [GGG][IG][8]
    float* c_s = sm + GGG * IG * 8;        // [GGG][16]

    int z = blockIdx.y;
    int n0 = blockIdx.x * GGG;
    const float* emb = (z == 0) ? e1 : (z == 1) ? e2 : e3;
    const float* st  = (z == 0) ? st1 : (z == 1) ? st2 : st3;

    int tid = threadIdx.x;
    if (tid < GGG * Dd) {
        int g = tid >> 4, d = tid & 15;
        c_s[tid] = emb[(n0 + g) * Dd + d] * me[z * Dd + d];
    }
    for (int idx = tid; idx < GGG * 8 * IG; idx += 128) {
        int i = idx % IG;
        int t = idx / IG;
        int g = t % GGG, b = t / GGG;
        x_s[(g * IG + i) * 8 + b] =
            g_xg[(((long)z * Bq + b) * Nn + n0 + g) * IG + i];
    }
    __syncthreads();

    int o = tid;
    float4 cr[GGG][4];
#pragma unroll
    for (int g = 0; g < GGG; g++) {
        const float4* cp = (const float4*)(c_s + g * 16);
#pragma unroll
        for (int q = 0; q < 4; q++) cr[g][q] = cp[q];
    }

    float acc[GGG][8];
#pragma unroll
    for (int g = 0; g < GGG; g++)
#pragma unroll
        for (int b = 0; b < 8; b++) acc[g][b] = 0.f;

    float wgv[16], wnx[16];
    {
        const float* wp = Wg + o;
#pragma unroll
        for (int d = 0; d < 16; d++) wnx[d] = wp[(long)d * IG * OG];
    }

    for (int i = 0; i < IG; i++) {
#pragma unroll
        for (int d = 0; d < 16; d++) wgv[d] = wnx[d];
        int ip = (i + 1 < IG) ? (i + 1) : i;
        const float* wp = Wg + (long)ip * OG + o;
#pragma unroll
        for (int d = 0; d < 16; d++) wnx[d] = wp[(long)d * IG * OG];

#pragma unroll
        for (int g = 0; g < GGG; g++) {
            float4 c0 = cr[g][0], c1 = cr[g][1], c2 = cr[g][2], c3 = cr[g][3];
            float w = c0.x * wgv[0] + c0.y * wgv[1] + c0.z * wgv[2] + c0.w * wgv[3]
                    + c1.x * wgv[4] + c1.y * wgv[5] + c1.z * wgv[6] + c1.w * wgv[7]
                    + c2.x * wgv[8] + c2.y * wgv[9] + c2.z * wgv[10] + c2.w * wgv[11]
                    + c3.x * wgv[12] + c3.y * wgv[13] + c3.z * wgv[14] + c3.w * wgv[15];
            float4 xa = *(const float4*)(x_s + (g * IG + i) * 8);
            float4 xb = *(const float4*)(x_s + (g * IG + i) * 8 + 4);
            acc[g][0] = fmaf(w, xa.x, acc[g][0]);
            acc[g][1] = fmaf(w, xa.y, acc[g][1]);
            acc[g][2] = fmaf(w, xa.z, acc[g][2]);
            acc[g][3] = fmaf(w, xa.w, acc[g][3]);
            acc[g][4] = fmaf(w, xb.x, acc[g][4]);
            acc[g][5] = fmaf(w, xb.y, acc[g][5]);
            acc[g][6] = fmaf(w, xb.z, acc[g][6]);
            acc[g][7] = fmaf(w, xb.w, acc[g][7]);
        }
    }

#pragma unroll
    for (int g = 0; g < GGG; g++) {
        int n = n0 + g;
        float4 c0 = cr[g][0], c1 = cr[g][1], c2 = cr[g][2], c3 = cr[g][3];
        const float* bp = Bg + o;
        float bias = c0.x * bp[0] + c0.y * bp[OG] + c0.z * bp[2 * OG] + c0.w * bp[3 * OG]
                   + c1.x * bp[4 * OG] + c1.y * bp[5 * OG] + c1.z * bp[6 * OG] + c1.w * bp[7 * OG]
                   + c2.x * bp[8 * OG] + c2.y * bp[9 * OG] + c2.z * bp[10 * OG] + c2.w * bp[11 * OG]
                   + c3.x * bp[12 * OG] + c3.y * bp[13 * OG] + c3.z * bp[14 * OG] + c3.w * bp[15 * OG];
#pragma unroll
        for (int b = 0; b < 8; b++) {
            float v = acc[g][b] + bias;
            float sg = 1.f / (1.f + __expf(-v));
            if (o < Hh) {
                float stv = st[((long)b * Nn + n) * Hh + o];
                float zs = sg * stv;
                g_xg[(((long)z * Bq + b) * Nn + n) * IG + CIN_ + o] = zs;
                g_P0[((long)z * NCOL + b * XIN_ + CIN_ + o) * Nn + n] = zs;
            } else {
                g_r[(((long)z * Bq + b) * Nn + n) * Hh + (o - Hh)] = sg;
            }
        }
    }
}

// ===========================================================================
// Kernel 4: fused update hypernet + GRU mix
// ===========================================================================
#define GGU 8
#define UPD_SMEM ((GGU * IG * 8 + GGU * Dd) * 4)

__global__ __launch_bounds__(128, 3)
void update_kernel(const float* __restrict__ e1, const float* __restrict__ e2,
                   const float* __restrict__ e3, const float* __restrict__ me,
                   const float* __restrict__ Wu, const float* __restrict__ Bu,
                   const float* __restrict__ st1, const float* __restrict__ st2,
                   const float* __restrict__ st3, float* __restrict__ out) {
    extern __shared__ float sm[];
    float* x_s = sm;
    float* c_s = sm + GGU * IG * 8;

    int z = blockIdx.y;
    int n0 = blockIdx.x * GGU;
    const float* emb = (z == 0) ? e1 : (z == 1) ? e2 : e3;
    const float* st  = (z == 0) ? st1 : (z == 1) ? st2 : st3;

    int tid = threadIdx.x;
    if (tid < GGU * Dd) {
        int g = tid >> 4, d = tid & 15;
        c_s[tid] = emb[(n0 + g) * Dd + d] * me[z * Dd + d];
    }
    for (int idx = tid; idx < GGU * 8 * IG; idx += 128) {
        int i = idx % IG;
        int t = idx / IG;
        int g = t % GGU, b = t / GGU;
        x_s[(g * IG + i) * 8 + b] =
            g_xg[(((long)z * Bq + b) * Nn + n0 + g) * IG + i];
    }
    __syncthreads();

    int o  = tid & 63;
    int gh = tid >> 6;
    int gbase = gh * 4;

    float4 cr[4][4];
#pragma unroll
    for (int g = 0; g < 4; g++) {
        const float4* cp = (const float4*)(c_s + (gbase + g) * 16);
#pragma unroll
        for (int q = 0; q < 4; q++) cr[g][q] = cp[q];
    }

    float acc[4][8];
#pragma unroll
    for (int g = 0; g < 4; g++)
#pragma unroll
        for (int b = 0; b < 8; b++) acc[g][b] = 0.f;

    float wgv[16], wnx[16];
    {
        const float* wp = Wu + o;
#pragma unroll
        for (int d = 0; d < 16; d++) wnx[d] = wp[(long)d * IG * OU];
    }

    for (int i = 0; i < IG; i++) {
#pragma unroll
        for (int d = 0; d < 16; d++) wgv[d] = wnx[d];
        int ip = (i + 1 < IG) ? (i + 1) : i;
        const float* wp = Wu + (long)ip * OU + o;
#pragma unroll
        for (int d = 0; d < 16; d++) wnx[d] = wp[(long)d * IG * OU];

#pragma unroll
        for (int g = 0; g < 4; g++) {
            float4 c0 = cr[g][0], c1 = cr[g][1], c2 = cr[g][2], c3 = cr[g][3];
            float w = c0.x * wgv[0] + c0.y * wgv[1] + c0.z * wgv[2] + c0.w * wgv[3]
                    + c1.x * wgv[4] + c1.y * wgv[5] + c1.z * wgv[6] + c1.w * wgv[7]
                    + c2.x * wgv[8] + c2.y * wgv[9] + c2.z * wgv[10] + c2.w * wgv[11]
                    + c3.x * wgv[12] + c3.y * wgv[13] + c3.z * wgv[14] + c3.w * wgv[15];
            const float* xp = x_s + ((gbase + g) * IG + i) * 8;
            float4 xa = *(const float4*)(xp);
            float4 xb = *(const float4*)(xp + 4);
            acc[g][0] = fmaf(w, xa.x, acc[g][0]);
            acc[g][1] = fmaf(w, xa.y, acc[g][1]);
            acc[g][2] = fmaf(w, xa.z, acc[g][2]);
            acc[g][3] = fmaf(w, xa.w, acc[g][3]);
            acc[g][4] = fmaf(w, xb.x, acc[g][4]);
            acc[g][5] = fmaf(w, xb.y, acc[g][5]);
            acc[g][6] = fmaf(w, xb.z, acc[g][6]);
            acc[g][7] = fmaf(w, xb.w, acc[g][7]);
        }
    }

#pragma unroll
    for (int g = 0; g < 4; g++) {
        int n = n0 + gbase + g;
        float4 c0 = cr[g][0], c1 = cr[g][1], c2 = cr[g][2], c3 = cr[g][3];
        const float* bp = Bu + o;
        float bias = c0.x * bp[0] + c0.y * bp[OU] + c0.z * bp[2 * OU] + c0.w * bp[3 * OU]
                   + c1.x * bp[4 * OU] + c1.y * bp[5 * OU] + c1.z * bp[6 * OU] + c1.w * bp[7 * OU]
                   + c2.x * bp[8 * OU] + c2.y * bp[9 * OU] + c2.z * bp[10 * OU] + c2.w * bp[11 * OU]
                   + c3.x * bp[12 * OU] + c3.y * bp[13 * OU] + c3.z * bp[14 * OU] + c3.w * bp[15 * OU];
#pragma unroll
        for (int b = 0; b < 8; b++) {
            float hc = tanhf(acc[g][b] + bias);
            long hidx = (((long)z * Bq + b) * Nn + n) * Hh + o;
            float r = g_r[hidx];
            float stv = st[((long)b * Nn + n) * Hh + o];
            out[hidx] = r * stv + (1.f - r) * hc;
        }
    }
}

// ===========================================================================
extern "C" void kernel_launch(void* const* d_in, const int* in_sizes, int n_in,
                              void* d_out, int out_size) {
    const float* x1 = (const float*)d_in[0];
    const float* x2 = (const float*)d_in[1];
    const float* x3 = (const float*)d_in[2];
    const float* s1 = (const float*)d_in[3];
    const float* s2 = (const float*)d_in[4];
    const float* s3 = (const float*)d_in[5];
    const float* A1 = (const float*)d_in[6];
    const float* A2 = (const float*)d_in[7];
    const float* A3 = (const float*)d_in[8];
    const float* e1 = (const float*)d_in[9];
    const float* e2 = (const float*)d_in[10];
    const float* e3 = (const float*)d_in[11];
    const float* me = (const float*)d_in[12];
    const float* Wg = (const float*)d_in[13];
    const float* Bg = (const float*)d_in[14];
    const float* Wu = (const float*)d_in[15];
    const float* Bu = (const float*)d_in[16];
    float* out = (float*)d_out;

    cudaFuncSetAttribute((const void*)gate_kernel,
                         cudaFuncAttributeMaxDynamicSharedMemorySize, GATE_SMEM);
    cudaFuncSetAttribute((const void*)update_kernel,
                         cudaFuncAttributeMaxDynamicSharedMemorySize, UPD_SMEM);

    float* P0;  cudaGetSymbolAddress((void**)&P0, g_P0);
    float* P1;  cudaGetSymbolAddress((void**)&P1, g_P1);

    dim3 gemm_grid(8, 5, 3);              // M-tiles x N-tiles x modes
    dim3 gg(Nn / GGG, 3);                 // 250 x 3
    dim3 gu(Nn / GGU, 3);                 // 125 x 3

    // ---- gate GCN ----
    concat_kernel<<<512, 256>>>(x1, x2, x3, s1, s2, s3);
    // t1 = S @ xs            -> g_xg[80:160] + packed P1
    gemm_tf32_kernel<<<gemm_grid, 256>>>(A1, A2, A3, P0, nullptr, P1, 80, 1.f, 0);
    // t2 = 2 S @ t1 - xs     -> g_xg[160:240]
    gemm_tf32_kernel<<<gemm_grid, 256>>>(A1, A2, A3, P1, P0, nullptr, 160, 2.f, 1);
    gate_kernel<<<gg, 128, GATE_SMEM>>>(e1, e2, e3, me, Wg, Bg, s1, s2, s3);
    // ---- candidate GCN (P0 cols 16:80 now hold z*state; cols 0:16 still x) ----
    gemm_tf32_kernel<<<gemm_grid, 256>>>(A1, A2, A3, P0, nullptr, P1, 80, 1.f, 0);
    gemm_tf32_kernel<<<gemm_grid, 256>>>(A1, A2, A3, P1, P0, nullptr, 160, 2.f, 1);
    update_kernel<<<gu, 128, UPD_SMEM>>>(e1, e2, e3, me, Wu, Bu, s1, s2, s3, out);
}